// round 5
// baseline (speedup 1.0000x reference)
#include <cuda_runtime.h>

// Rotated ROI cropper v5:
//   x:     [8, 3, 1024, 1024] fp32
//   boxes: [8, 64, 5] fp32  (cx, cy, w, h, angle_deg)
//   out:   [512, 3, 48, 320] fp32
//
// Block = one 32x24 output tile of one box (3 rows per thread).
// Source bbox of a 32x24 tile is <= 43 px/side (bw<=300, bh<=60, |ang|<=45);
// staged with a 1-px guard border in a 45x47 smem tile (split planes:
// float2 (c0,c1) + float c2). Guard border replaces per-pixel clamps;
// a single flat-index clamp keeps memory safety for out-of-spec data.

#define IMG_H 1024
#define IMG_W 1024
#define OUT_H 48
#define OUT_W 320
#define CHANS 3
#define N_BOXES_TOTAL 512
#define PLANE (IMG_H * IMG_W)
#define OPLANE (OUT_H * OUT_W)

#define TILE_OX 32
#define TILE_OY 24
#define NTX (OUT_W / TILE_OX)   // 10
#define NTY (OUT_H / TILE_OY)   // 2

#define STILE  45
#define SPITCH 47
#define IDX_LIM ((STILE - 2) * SPITCH + (STILE - 2))

#define NTHREADS 256

__global__ __launch_bounds__(NTHREADS)
void rotated_roi_crop_v5(const float* __restrict__ x,
                         const float* __restrict__ boxes,
                         float* __restrict__ out) {
    __shared__ float2 tileAB[STILE][SPITCH];  // (c0, c1)
    __shared__ float  tileC [STILE][SPITCH];  // c2

    const int bid     = blockIdx.x;
    const int tx_tile = bid % NTX;
    const int ty_tile = (bid / NTX) % NTY;
    const int g       = bid / (NTX * NTY);

    // ---- box params (uniform broadcast) ----
    const float* bp = boxes + g * 5;
    const float cx  = bp[0];
    const float cy  = bp[1];
    const float bw  = bp[2];
    const float bh  = bp[3];
    const float ang = bp[4];

    const float theta = -ang * 0.017453292519943295f;
    float s_, c_;
    sincosf(theta, &s_, &c_);
    const float b = c_ * 0.5f;
    const float a = s_ * 0.5f;

    const float p0x = cx - a * bh - b * bw;
    const float p0y = cy + b * bh - a * bw;
    const float p1x = cx + a * bh - b * bw;
    const float p1y = cy - b * bh - a * bw;
    const float p2x = 2.0f * cx - p0x;
    const float p2y = 2.0f * cy - p0y;

    const float ex_x = p2x - p1x;   // source delta per unit u
    const float ex_y = p2y - p1y;
    const float ey_x = p0x - p1x;   // source delta per unit v
    const float ey_y = p0y - p1y;

    // ---- source bbox of this tile (4 affine corners) ----
    const float u0 = (float)(tx_tile * TILE_OX)               * (1.0f / OUT_W);
    const float u1 = (float)(tx_tile * TILE_OX + TILE_OX - 1) * (1.0f / OUT_W);
    const float v0 = (float)(ty_tile * TILE_OY)               * (1.0f / OUT_H);
    const float v1 = (float)(ty_tile * TILE_OY + TILE_OY - 1) * (1.0f / OUT_H);

    const float sxa = p1x + u0 * ex_x + v0 * ey_x;
    const float sxb = p1x + u1 * ex_x + v0 * ey_x;
    const float sxc = p1x + u0 * ex_x + v1 * ey_x;
    const float sxd = p1x + u1 * ex_x + v1 * ey_x;
    const float sya = p1y + u0 * ex_y + v0 * ey_y;
    const float syb = p1y + u1 * ex_y + v0 * ey_y;
    const float syc = p1y + u0 * ex_y + v1 * ey_y;
    const float syd = p1y + u1 * ex_y + v1 * ey_y;

    const int fmin_x = (int)floorf(fminf(fminf(sxa, sxb), fminf(sxc, sxd)));
    const int fmax_x = (int)floorf(fmaxf(fmaxf(sxa, sxb), fmaxf(sxc, sxd)));
    const int fmin_y = (int)floorf(fminf(fminf(sya, syb), fminf(syc, syd)));
    const int fmax_y = (int)floorf(fmaxf(fmaxf(sya, syb), fmaxf(syc, syd)));

    const int x_org = fmin_x - 1;                       // 1-px guard
    const int y_org = fmin_y - 1;
    const int bwid = min(fmax_x - fmin_x + 4, STILE);   // taps + guard + fp slack
    const int bhei = min(fmax_y - fmin_y + 4, STILE);

    const int lane = threadIdx.x & 31;
    const int wrp  = threadIdx.x >> 5;   // 0..7

    // ---- staged load: warp-row-strided, zero-fill outside image ----
    const int batch = g >> 6;
    const float* img = x + (size_t)batch * CHANS * PLANE;
    const bool wide = (bwid > 32);

    for (int yy = wrp; yy < bhei; yy += 8) {
        const int gy = y_org + yy;
        const bool rok = ((unsigned)gy < IMG_H);
        const float* rp = img + (size_t)gy * IMG_W;

        {
            const int xx = lane;
            const int gx = x_org + xx;
            const bool ok = rok & ((unsigned)gx < IMG_W) & (xx < bwid);
            float c0 = 0.f, c1 = 0.f, c2 = 0.f;
            if (ok) {
                c0 = __ldg(rp + gx);
                c1 = __ldg(rp + gx + PLANE);
                c2 = __ldg(rp + gx + 2 * PLANE);
            }
            tileAB[yy][xx] = make_float2(c0, c1);
            tileC [yy][xx] = c2;
        }
        if (wide) {
            const int xx = 32 + lane;
            if (xx < bwid) {
                const int gx = x_org + xx;
                const bool ok = rok & ((unsigned)gx < IMG_W);
                float c0 = 0.f, c1 = 0.f, c2 = 0.f;
                if (ok) {
                    c0 = __ldg(rp + gx);
                    c1 = __ldg(rp + gx + PLANE);
                    c2 = __ldg(rp + gx + 2 * PLANE);
                }
                tileAB[yy][xx] = make_float2(c0, c1);
                tileC [yy][xx] = c2;
            }
        }
    }
    __syncthreads();

    // ---- compute: warp = 32 contiguous output px; 3 rows per thread ----
    const int ox = tx_tile * TILE_OX + lane;
    const int oy0 = ty_tile * TILE_OY + wrp * 3;

    const float u = (float)ox * (1.0f / OUT_W);
    const float vb = (float)oy0 * (1.0f / OUT_H);

    // local (tile-relative) source coords; origin folded in once
    float sx = fmaf(vb, ey_x, fmaf(u, ex_x, p1x)) - (float)x_org;
    float sy = fmaf(vb, ey_y, fmaf(u, ex_y, p1y)) - (float)y_org;
    const float dvx = ey_x * (1.0f / OUT_H);
    const float dvy = ey_y * (1.0f / OUT_H);

    const float2* __restrict__ tAB = &tileAB[0][0];
    const float*  __restrict__ tC  = &tileC[0][0];

    float* ob = out + (((size_t)g * CHANS) * OUT_H + oy0) * OUT_W + ox;

#pragma unroll
    for (int r = 0; r < 3; r++) {
        const float x0f = floorf(sx);
        const float y0f = floorf(sy);
        const float dx = sx - x0f;
        const float dy = sy - y0f;

        int idx = (int)y0f * SPITCH + (int)x0f;
        idx = min(max(idx, 0), IDX_LIM);   // memory safety only; never binds in-spec

        const float omdx = 1.0f - dx;
        const float omdy = 1.0f - dy;
        const float w00 = omdx * omdy;
        const float w10 = dx * omdy;
        const float w01 = omdx * dy;
        const float w11 = dx * dy;

        const float2 t00 = tAB[idx];
        const float2 t10 = tAB[idx + 1];
        const float2 t01 = tAB[idx + SPITCH];
        const float2 t11 = tAB[idx + SPITCH + 1];
        const float  c00 = tC[idx];
        const float  c10 = tC[idx + 1];
        const float  c01 = tC[idx + SPITCH];
        const float  c11 = tC[idx + SPITCH + 1];

        const float r0 = fmaf(t11.x, w11, fmaf(t01.x, w01, fmaf(t10.x, w10, t00.x * w00)));
        const float r1 = fmaf(t11.y, w11, fmaf(t01.y, w01, fmaf(t10.y, w10, t00.y * w00)));
        const float r2 = fmaf(c11,   w11, fmaf(c01,   w01, fmaf(c10,   w10, c00   * w00)));

        ob[0]          = r0;
        ob[OPLANE]     = r1;
        ob[2 * OPLANE] = r2;

        sx += dvx;
        sy += dvy;
        ob += OUT_W;
    }
}

extern "C" void kernel_launch(void* const* d_in, const int* in_sizes, int n_in,
                              void* d_out, int out_size) {
    const float* x     = (const float*)d_in[0];
    const float* boxes = (const float*)d_in[1];
    float* out         = (float*)d_out;

    dim3 grid(N_BOXES_TOTAL * NTX * NTY);   // 10240
    dim3 block(NTHREADS);
    rotated_roi_crop_v5<<<grid, block>>>(x, boxes, out);
}